// round 4
// baseline (speedup 1.0000x reference)
#include <cuda_runtime.h>
#include <cuda_bf16.h>

#define BQ   256
#define TT   512
#define EE   128
#define HH   256
#define NB   32     // batches per group
#define NGRP 8      // groups per direction
#define NCTA 8      // j-split CTAs per group
#define ROWS 96     // gate rows per CTA (3 gates x 32 cols)
#define NTH  192    // threads per CTA (24 row-quads x 8 nb-groups)
#define KTOT 384
#define KIN  128
#define PREP 34     // padded row stride for pre-act arrays

typedef unsigned long long u64;

// ---------------- device scratch ----------------
__device__ float g_wprep[2 * NCTA * KTOT * ROWS];  // [dir][cta][k][row]
__device__ float g_fc1T[512 * 128];
__device__ float g_fc2T[128 * 64];
__device__ float g_h[BQ * 2 * HH];
__device__ int   g_order[BQ];
__device__ float g_hx[2 * NGRP * 2 * HH * NB];     // [dir][grp][parity][col][nb]
__device__ int   g_flag[2 * NGRP * NCTA];

// ---------------- helpers ----------------
__device__ __forceinline__ u64 ffma2(u64 a, u64 b, u64 c) {
    u64 d; asm("fma.rn.f32x2 %0, %1, %2, %3;" : "=l"(d) : "l"(a), "l"(b), "l"(c)); return d;
}
__device__ __forceinline__ u64 pack2(float lo, float hi) {
    u64 d; asm("mov.b64 %0, {%1, %2};" : "=l"(d) : "f"(lo), "f"(hi)); return d;
}
__device__ __forceinline__ float sigf(float x) { return __fdividef(1.0f, 1.0f + __expf(-x)); }
__device__ __forceinline__ float tanhfast(float x) { return 1.0f - __fdividef(2.0f, __expf(2.0f * x) + 1.0f); }

// SMEM offsets (bytes)
#define OFF_W    0
#define OFF_XIN  147456
#define OFF_PX   196608
#define OFF_PH   209664
#define OFF_BIH  222720
#define OFF_BHH  223104
#define OFF_OB   223488
#define OFF_LEN  223616
#define SMEM_SZ  223744

// ---------------- prep: repack weights + fc transposes + zero flags ----------------
__global__ void prep_kernel(const float* __restrict__ wihf, const float* __restrict__ whhf,
                            const float* __restrict__ wihb, const float* __restrict__ whhb,
                            const float* __restrict__ fc1w, const float* __restrict__ fc2w) {
    int idx = blockIdx.x * blockDim.x + threadIdx.x;
    const int NW = 2 * NCTA * KTOT * ROWS;             // 589824
    const int B1 = NW, B2 = B1 + 512 * 128, B3 = B2 + 128 * 64, B4 = B3 + 2 * NGRP * NCTA;
    if (idx < NW) {
        int r   = idx % ROWS;
        int k   = (idx / ROWS) % KTOT;
        int cta = (idx / (ROWS * KTOT)) % NCTA;
        int dir = idx / (ROWS * KTOT * NCTA);
        const float* wih = dir ? wihb : wihf;
        const float* whh = dir ? whhb : whhf;
        int grow = (r >> 5) * HH + cta * 32 + (r & 31);   // gate*256 + col
        g_wprep[idx] = (k < KIN) ? wih[grow * EE + k] : whh[grow * HH + (k - KIN)];
    } else if (idx < B2) {
        int o = idx - B1; int k = o / 128, i = o % 128;
        g_fc1T[o] = fc1w[i * 512 + k];
    } else if (idx < B3) {
        int o = idx - B2; int k = o / 64, i = o % 64;
        g_fc2T[o] = fc2w[i * 128 + k];
    } else if (idx < B4) {
        g_flag[idx - B3] = 0;
    }
}

// ---------------- sort batch by length (ascending bitonic) ----------------
__global__ void sort_kernel(const int* __restrict__ lengths) {
    __shared__ int key[BQ], val[BQ];
    unsigned t = threadIdx.x;
    key[t] = lengths[t]; val[t] = (int)t;
    __syncthreads();
    for (unsigned size = 2; size <= BQ; size <<= 1) {
        for (unsigned stride = size >> 1; stride > 0; stride >>= 1) {
            __syncthreads();
            unsigned j = t ^ stride;
            if (j > t) {
                bool up = ((t & size) == 0);
                int kt = key[t], kj = key[j];
                if ((kt > kj) == up) {
                    key[t] = kj; key[j] = kt;
                    int vt = val[t]; val[t] = val[j]; val[j] = vt;
                }
            }
        }
    }
    __syncthreads();
    g_order[t] = val[t];
}

// ---------------- GRU: 8 cooperating CTAs per (dir, group), SMEM-resident weights ----------------
__global__ __launch_bounds__(NTH, 1) void gru_kernel(
    const int* __restrict__ x, const int* __restrict__ lengths,
    const float* __restrict__ emb,
    const float* __restrict__ bih_f, const float* __restrict__ bhh_f,
    const float* __restrict__ bih_b, const float* __restrict__ bhh_b) {

    const int cta = blockIdx.x, grp = blockIdx.y, dir = blockIdx.z;
    const int tid = threadIdx.x;
    const int q4 = (tid >> 3) * 4;      // row base (0..92)
    const int n4 = (tid & 7) * 4;       // nb base (0..28)

    extern __shared__ __align__(16) char sm[];
    float* w_s   = (float*)(sm + OFF_W);      // [384][96]
    float* xin   = (float*)(sm + OFF_XIN);    // [384][32]  (k 0..127 = emb, 128..383 = h)
    float* preX  = (float*)(sm + OFF_PX);     // [96][34]
    float* preH  = (float*)(sm + OFF_PH);     // [96][34]
    float* bih_s = (float*)(sm + OFF_BIH);    // [96]
    float* bhh_s = (float*)(sm + OFF_BHH);    // [96]
    int*   ob_s  = (int*)(sm + OFF_OB);       // [32]
    int*   len_s = (int*)(sm + OFF_LEN);      // [32]

    const float* bih = dir ? bih_b : bih_f;
    const float* bhh = dir ? bhh_b : bhh_f;

    if (tid < NB) {
        int o = g_order[grp * NB + tid];
        ob_s[tid] = o;
        len_s[tid] = lengths[o];
    }
    if (tid < ROWS) {
        int grow = (tid >> 5) * HH + cta * 32 + (tid & 31);
        bih_s[tid] = bih[grow];
        bhh_s[tid] = bhh[grow];
    }
    // load weight slice into SMEM (one-time)
    {
        const float4* wp = (const float4*)(g_wprep + (size_t)(dir * NCTA + cta) * KTOT * ROWS);
        float4* wd = (float4*)w_s;
        for (int i = tid; i < KTOT * ROWS / 4; i += NTH) wd[i] = wp[i];
    }
    // zero hidden part of xin
    for (int i = tid; i < HH * NB; i += NTH) xin[KIN * NB + i] = 0.0f;
    __syncthreads();

    const int M = len_s[NB - 1];   // ascending sort -> max is last
    const int fbase = (dir * NGRP + grp) * NCTA;
    float* hx_grp = g_hx + (size_t)(dir * NGRP + grp) * 2 * HH * NB;

    // prologue: gather embedding for step 0
    {
        int t0 = dir ? (M - 1) : 0;
        for (int idx = tid; idx < 1024; idx += NTH) {
            int nb = idx >> 5, ch = idx & 31;
            int tok = x[ob_s[nb] * TT + t0];
            float4 v = *(const float4*)(emb + (size_t)tok * EE + ch * 4);
            xin[(ch * 4 + 0) * NB + nb] = v.x;
            xin[(ch * 4 + 1) * NB + nb] = v.y;
            xin[(ch * 4 + 2) * NB + nb] = v.z;
            xin[(ch * 4 + 3) * NB + nb] = v.w;
        }
    }
    __syncthreads();

    for (int s = 0; s < M; s++) {
        // ---- A: input projection (k = 0..127) ----
        {
            u64 acc[4][2];
#pragma unroll
            for (int r = 0; r < 4; r++) { acc[r][0] = 0ull; acc[r][1] = 0ull; }
#pragma unroll 4
            for (int k = 0; k < KIN; k++) {
                float4 wv = *(const float4*)(w_s + k * ROWS + q4);
                ulonglong2 xv = *(const ulonglong2*)(xin + k * NB + n4);
                u64 w0 = pack2(wv.x, wv.x), w1 = pack2(wv.y, wv.y);
                u64 w2 = pack2(wv.z, wv.z), w3 = pack2(wv.w, wv.w);
                acc[0][0] = ffma2(w0, xv.x, acc[0][0]); acc[0][1] = ffma2(w0, xv.y, acc[0][1]);
                acc[1][0] = ffma2(w1, xv.x, acc[1][0]); acc[1][1] = ffma2(w1, xv.y, acc[1][1]);
                acc[2][0] = ffma2(w2, xv.x, acc[2][0]); acc[2][1] = ffma2(w2, xv.y, acc[2][1]);
                acc[3][0] = ffma2(w3, xv.x, acc[3][0]); acc[3][1] = ffma2(w3, xv.y, acc[3][1]);
            }
#pragma unroll
            for (int r = 0; r < 4; r++) {
                *(u64*)(preX + (q4 + r) * PREP + n4)     = acc[r][0];
                *(u64*)(preX + (q4 + r) * PREP + n4 + 2) = acc[r][1];
            }
        }
        __syncthreads();

        // ---- B: wait for peers' h^s ----
        if (s > 0 && tid < NCTA) {
            const int* fp = &g_flag[fbase + tid];
            int v;
            do { asm volatile("ld.acquire.gpu.s32 %0, [%1];" : "=r"(v) : "l"(fp)); } while (v < s);
        }
        __syncthreads();

        // ---- C: copy h^s into xin hidden part; gather next embedding ----
        if (s > 0) {
            const float4* src = (const float4*)(hx_grp + (size_t)(s & 1) * HH * NB);
            float4* dst = (float4*)(xin + KIN * NB);
            for (int i = tid; i < HH * NB / 4; i += NTH) dst[i] = src[i];
        }
        if (s + 1 < M) {
            int tn = dir ? (M - 2 - s) : (s + 1);
            for (int idx = tid; idx < 1024; idx += NTH) {
                int nb = idx >> 5, ch = idx & 31;
                int tok = x[ob_s[nb] * TT + tn];
                float4 v = *(const float4*)(emb + (size_t)tok * EE + ch * 4);
                xin[(ch * 4 + 0) * NB + nb] = v.x;
                xin[(ch * 4 + 1) * NB + nb] = v.y;
                xin[(ch * 4 + 2) * NB + nb] = v.z;
                xin[(ch * 4 + 3) * NB + nb] = v.w;
            }
        }
        __syncthreads();

        // ---- D: hidden projection (k = 128..383) ----
        {
            u64 acc[4][2];
#pragma unroll
            for (int r = 0; r < 4; r++) { acc[r][0] = 0ull; acc[r][1] = 0ull; }
#pragma unroll 4
            for (int k = KIN; k < KTOT; k++) {
                float4 wv = *(const float4*)(w_s + k * ROWS + q4);
                ulonglong2 xv = *(const ulonglong2*)(xin + k * NB + n4);
                u64 w0 = pack2(wv.x, wv.x), w1 = pack2(wv.y, wv.y);
                u64 w2 = pack2(wv.z, wv.z), w3 = pack2(wv.w, wv.w);
                acc[0][0] = ffma2(w0, xv.x, acc[0][0]); acc[0][1] = ffma2(w0, xv.y, acc[0][1]);
                acc[1][0] = ffma2(w1, xv.x, acc[1][0]); acc[1][1] = ffma2(w1, xv.y, acc[1][1]);
                acc[2][0] = ffma2(w2, xv.x, acc[2][0]); acc[2][1] = ffma2(w2, xv.y, acc[2][1]);
                acc[3][0] = ffma2(w3, xv.x, acc[3][0]); acc[3][1] = ffma2(w3, xv.y, acc[3][1]);
            }
#pragma unroll
            for (int r = 0; r < 4; r++) {
                *(u64*)(preH + (q4 + r) * PREP + n4)     = acc[r][0];
                *(u64*)(preH + (q4 + r) * PREP + n4 + 2) = acc[r][1];
            }
        }
        __syncthreads();

        // ---- E: gates + combine + publish h^{s+1} ----
        {
            float* hxw = hx_grp + (size_t)((s + 1) & 1) * HH * NB + cta * 32 * NB;
            const int t = dir ? (M - 1 - s) : s;
            for (int idx = tid; idx < 32 * NB; idx += NTH) {
                int col = idx >> 5, nb = idx & 31;
                int pr = col, pz = 32 + col, pn = 64 + col;
                float xr = preX[pr * PREP + nb] + bih_s[pr];
                float hr = preH[pr * PREP + nb] + bhh_s[pr];
                float xz = preX[pz * PREP + nb] + bih_s[pz];
                float hz = preH[pz * PREP + nb] + bhh_s[pz];
                float xn = preX[pn * PREP + nb] + bih_s[pn];
                float hn = preH[pn * PREP + nb] + bhh_s[pn];
                float r  = sigf(xr + hr);
                float z  = sigf(xz + hz);
                float nv = tanhfast(xn + r * hn);
                float hold = xin[(KIN + cta * 32 + col) * NB + nb];
                float hnew = (t < len_s[nb]) ? ((1.0f - z) * nv + z * hold) : hold;
                hxw[col * NB + nb] = hnew;
            }
        }
        __threadfence();
        __syncthreads();
        if (tid == 0) {
            int v = s + 1;
            asm volatile("st.release.gpu.s32 [%0], %1;" :: "l"(&g_flag[fbase + cta]), "r"(v));
        }
    }

    // epilogue: write own 32 columns of final h (h^M lives in parity M&1)
    {
        const float* hsrc = hx_grp + (size_t)(M & 1) * HH * NB + cta * 32 * NB;
        for (int idx = tid; idx < 32 * NB; idx += NTH) {
            int col = idx >> 5, nb = idx & 31;
            g_h[(size_t)ob_s[nb] * (2 * HH) + dir * HH + cta * 32 + col] = hsrc[col * NB + nb];
        }
    }
}

// ---------------- head: fc1 + relu + fc2 + L2 normalize ----------------
__global__ __launch_bounds__(128) void head_kernel(const float* __restrict__ fc1_b,
                                                   const float* __restrict__ fc2_b,
                                                   float* __restrict__ out) {
    __shared__ float hsm[512];
    __shared__ float hid[128];
    __shared__ float osm[64];
    __shared__ float inv_s;
    const int b = blockIdx.x, t = threadIdx.x;

    ((float4*)hsm)[t] = ((const float4*)(g_h + (size_t)b * 512))[t];
    __syncthreads();

    float acc = fc1_b[t];
#pragma unroll 8
    for (int k = 0; k < 512; k++) acc += g_fc1T[k * 128 + t] * hsm[k];
    hid[t] = fmaxf(acc, 0.0f);
    __syncthreads();

    if (t < 64) {
        float a = fc2_b[t];
#pragma unroll 8
        for (int k = 0; k < 128; k++) a += g_fc2T[k * 64 + t] * hid[k];
        osm[t] = a;
    }
    __syncthreads();
    if (t == 0) {
        float ss = 0.0f;
        for (int o = 0; o < 64; o++) ss += osm[o] * osm[o];
        inv_s = 1.0f / fmaxf(sqrtf(ss), 1e-12f);
    }
    __syncthreads();
    if (t < 64) out[b * 64 + t] = osm[t] * inv_s;
}

// ---------------- launch ----------------
extern "C" void kernel_launch(void* const* d_in, const int* in_sizes, int n_in,
                              void* d_out, int out_size) {
    const int*   x        = (const int*)d_in[0];
    const int*   lengths  = (const int*)d_in[1];
    const float* emb      = (const float*)d_in[2];
    const float* w_ih_f   = (const float*)d_in[3];
    const float* w_hh_f   = (const float*)d_in[4];
    const float* b_ih_f   = (const float*)d_in[5];
    const float* b_hh_f   = (const float*)d_in[6];
    const float* w_ih_b   = (const float*)d_in[7];
    const float* w_hh_b   = (const float*)d_in[8];
    const float* b_ih_b   = (const float*)d_in[9];
    const float* b_hh_b   = (const float*)d_in[10];
    const float* fc1_w    = (const float*)d_in[11];
    const float* fc1_b    = (const float*)d_in[12];
    const float* fc2_w    = (const float*)d_in[13];
    const float* fc2_b    = (const float*)d_in[14];
    float* out = (float*)d_out;

    static bool attr_set = false;
    if (!attr_set) {
        cudaFuncSetAttribute(gru_kernel, cudaFuncAttributeMaxDynamicSharedMemorySize, SMEM_SZ);
        attr_set = true;
    }

    const int total = 2 * NCTA * KTOT * ROWS + 512 * 128 + 128 * 64 + 2 * NGRP * NCTA;
    prep_kernel<<<(total + 255) / 256, 256>>>(w_ih_f, w_hh_f, w_ih_b, w_hh_b, fc1_w, fc2_w);
    sort_kernel<<<1, BQ>>>(lengths);
    dim3 gg(NCTA, NGRP, 2);
    gru_kernel<<<gg, NTH, SMEM_SZ>>>(x, lengths, emb, b_ih_f, b_hh_f, b_ih_b, b_hh_b);
    head_kernel<<<BQ, 128>>>(fc1_b, fc2_b, out);
}